// round 1
// baseline (speedup 1.0000x reference)
#include <cuda_runtime.h>
#include <cuda_bf16.h>

// Shapes (fixed for this problem)
//  x: [4, 2048, 768], W_qkv: [768, 2304], b_qkv: [2304], W_o: [768,768], b_o: [768]
//  out: [4, 2048, 768]
#define BATCH 4
#define SEQ   2048
#define DMODEL 768
#define NHEAD 12
#define HDIM  64

// Scratch (device globals: allocation-free rule)
__device__ float g_q[BATCH * NHEAD * SEQ * HDIM];     // [B,H,T,hd]
__device__ float g_k[BATCH * NHEAD * SEQ * HDIM];
__device__ float g_v[BATCH * NHEAD * SEQ * HDIM];
__device__ float g_att[BATCH * SEQ * DMODEL];         // [B,T,D]

// ---------------------------------------------------------------------------
// SGEMM 128x128x8, 256 threads, 8x8 per-thread microtile.
// Kernel 1: X[8192,768] @ W_qkv[768,2304] + b -> scatter to g_q/g_k/g_v
// ---------------------------------------------------------------------------
__global__ __launch_bounds__(256) void sgemm_qkv_kernel(
    const float* __restrict__ A,      // [8192, 768]
    const float* __restrict__ W,      // [768, 2304]
    const float* __restrict__ bias)   // [2304]
{
    __shared__ float As[8][128];   // transposed: As[k][m]
    __shared__ float Bs[8][128];   // Bs[k][n]

    const int bm = blockIdx.y * 128;
    const int bn = blockIdx.x * 128;
    const int tid = threadIdx.x;
    const int tr = tid / 16;          // 0..15
    const int tc = tid % 16;          // 0..15
    const int aRow = tid >> 1;        // 0..127
    const int aCol = (tid & 1) * 4;   // 0 or 4
    const int bRow = tid >> 5;        // 0..7
    const int bCol = (tid & 31) * 4;  // 0..124

    float acc[8][8];
#pragma unroll
    for (int i = 0; i < 8; i++)
#pragma unroll
        for (int j = 0; j < 8; j++) acc[i][j] = 0.f;

    for (int k0 = 0; k0 < DMODEL; k0 += 8) {
        float4 av = *(const float4*)&A[(size_t)(bm + aRow) * DMODEL + k0 + aCol];
        As[aCol + 0][aRow] = av.x;
        As[aCol + 1][aRow] = av.y;
        As[aCol + 2][aRow] = av.z;
        As[aCol + 3][aRow] = av.w;
        float4 bv = *(const float4*)&W[(size_t)(k0 + bRow) * 2304 + bn + bCol];
        *(float4*)&Bs[bRow][bCol] = bv;
        __syncthreads();

#pragma unroll
        for (int k = 0; k < 8; k++) {
            float a[8], b[8];
            *(float4*)&a[0] = *(const float4*)&As[k][tr * 8];
            *(float4*)&a[4] = *(const float4*)&As[k][tr * 8 + 4];
            *(float4*)&b[0] = *(const float4*)&Bs[k][tc * 8];
            *(float4*)&b[4] = *(const float4*)&Bs[k][tc * 8 + 4];
#pragma unroll
            for (int i = 0; i < 8; i++)
#pragma unroll
                for (int j = 0; j < 8; j++) acc[i][j] += a[i] * b[j];
        }
        __syncthreads();
    }

    // Epilogue: scatter to Q/K/V in [B,H,T,hd] layout
#pragma unroll
    for (int i = 0; i < 8; i++) {
        const int m = bm + tr * 8 + i;
        const int b = m >> 11;          // /2048
        const int t = m & 2047;
#pragma unroll
        for (int j = 0; j < 8; j++) {
            const int n = bn + tc * 8 + j;
            const float val = acc[i][j] + bias[n];
            const int sel = n / DMODEL;          // 0,1,2 (uniform per block)
            const int c = n - sel * DMODEL;
            const int h = c >> 6;
            const int d = c & 63;
            float* dst = (sel == 0) ? g_q : (sel == 1) ? g_k : g_v;
            dst[(((size_t)(b * NHEAD + h)) * SEQ + t) * HDIM + d] = val;
        }
    }
}

// ---------------------------------------------------------------------------
// Kernel 3: g_att[8192,768] @ W_o[768,768] + b_o -> out
// ---------------------------------------------------------------------------
__global__ __launch_bounds__(256) void sgemm_out_kernel(
    const float* __restrict__ W,      // [768, 768]
    const float* __restrict__ bias,   // [768]
    float* __restrict__ out)          // [8192, 768]
{
    __shared__ float As[8][128];
    __shared__ float Bs[8][128];

    const int bm = blockIdx.y * 128;
    const int bn = blockIdx.x * 128;
    const int tid = threadIdx.x;
    const int tr = tid / 16;
    const int tc = tid % 16;
    const int aRow = tid >> 1;
    const int aCol = (tid & 1) * 4;
    const int bRow = tid >> 5;
    const int bCol = (tid & 31) * 4;

    float acc[8][8];
#pragma unroll
    for (int i = 0; i < 8; i++)
#pragma unroll
        for (int j = 0; j < 8; j++) acc[i][j] = 0.f;

    for (int k0 = 0; k0 < DMODEL; k0 += 8) {
        float4 av = *(const float4*)&g_att[(size_t)(bm + aRow) * DMODEL + k0 + aCol];
        As[aCol + 0][aRow] = av.x;
        As[aCol + 1][aRow] = av.y;
        As[aCol + 2][aRow] = av.z;
        As[aCol + 3][aRow] = av.w;
        float4 bv = *(const float4*)&W[(size_t)(k0 + bRow) * DMODEL + bn + bCol];
        *(float4*)&Bs[bRow][bCol] = bv;
        __syncthreads();

#pragma unroll
        for (int k = 0; k < 8; k++) {
            float a[8], b[8];
            *(float4*)&a[0] = *(const float4*)&As[k][tr * 8];
            *(float4*)&a[4] = *(const float4*)&As[k][tr * 8 + 4];
            *(float4*)&b[0] = *(const float4*)&Bs[k][tc * 8];
            *(float4*)&b[4] = *(const float4*)&Bs[k][tc * 8 + 4];
#pragma unroll
            for (int i = 0; i < 8; i++)
#pragma unroll
                for (int j = 0; j < 8; j++) acc[i][j] += a[i] * b[j];
        }
        __syncthreads();
    }

#pragma unroll
    for (int i = 0; i < 8; i++) {
        const int m = bm + tr * 8 + i;
#pragma unroll
        for (int j = 0; j < 8; j++) {
            const int n = bn + tc * 8 + j;
            out[(size_t)m * DMODEL + n] = acc[i][j] + bias[n];
        }
    }
}

// ---------------------------------------------------------------------------
// Kernel 2: flash attention, fp32, causal.
// Block = 64 queries for one (b,h). 256 threads = 16x16 grid, 4x4 microtiles.
// Smem: Qs[64][65], Ks[64][65] (aliased as Ps after S-phase), Vs[64][65].
// ---------------------------------------------------------------------------
#define APAD 65
#define ASZ (64 * APAD)

__global__ __launch_bounds__(256) void attn_kernel() {
    extern __shared__ float sm[];
    float* Qs = sm;             // [64][65] row=query, col=d
    float* Ks = sm + ASZ;       // [64][65] row=key,   col=d   (later: Ps[q][key])
    float* Vs = sm + 2 * ASZ;   // [64][65] row=key,   col=d

    const int tq = blockIdx.x;            // q-tile 0..31
    const int bh = blockIdx.y;            // 0..47 = b*12+h
    const int q0 = tq * 64;
    const float* Qg = g_q + (size_t)bh * SEQ * HDIM;
    const float* Kg = g_k + (size_t)bh * SEQ * HDIM;
    const float* Vg = g_v + (size_t)bh * SEQ * HDIM;

    const int tid = threadIdx.x;
    const int ty = tid >> 4;   // 0..15, owns query rows ty*4..ty*4+3
    const int tx = tid & 15;   // 0..15, owns cols tx*4..tx*4+3

    // Load Q tile
#pragma unroll
    for (int r = 0; r < 4; r++) {
        const int f = tid + 256 * r;
        const int row = f >> 4;
        const int d0 = (f & 15) * 4;
        float4 q = *(const float4*)&Qg[(size_t)(q0 + row) * HDIM + d0];
        float* p = &Qs[row * APAD + d0];
        p[0] = q.x; p[1] = q.y; p[2] = q.z; p[3] = q.w;
    }

    float o[4][4];
    float mrow[4], lrow[4];
#pragma unroll
    for (int i = 0; i < 4; i++) {
        mrow[i] = -1e30f;
        lrow[i] = 0.f;
#pragma unroll
        for (int j = 0; j < 4; j++) o[i][j] = 0.f;
    }
    __syncthreads();

    for (int tk = 0; tk <= tq; ++tk) {
        const int k0 = tk * 64;
        // Load K,V tiles
#pragma unroll
        for (int r = 0; r < 4; r++) {
            const int f = tid + 256 * r;
            const int row = f >> 4;
            const int d0 = (f & 15) * 4;
            float4 kv = *(const float4*)&Kg[(size_t)(k0 + row) * HDIM + d0];
            float4 vv = *(const float4*)&Vg[(size_t)(k0 + row) * HDIM + d0];
            float* pk = &Ks[row * APAD + d0];
            pk[0] = kv.x; pk[1] = kv.y; pk[2] = kv.z; pk[3] = kv.w;
            float* pv = &Vs[row * APAD + d0];
            pv[0] = vv.x; pv[1] = vv.y; pv[2] = vv.z; pv[3] = vv.w;
        }
        __syncthreads();

        // S = Q K^T  (4x4 per thread)
        float s[4][4];
#pragma unroll
        for (int i = 0; i < 4; i++)
#pragma unroll
            for (int j = 0; j < 4; j++) s[i][j] = 0.f;

#pragma unroll 16
        for (int d = 0; d < HDIM; ++d) {
            float qv[4], kv[4];
#pragma unroll
            for (int i = 0; i < 4; i++) qv[i] = Qs[(ty * 4 + i) * APAD + d];
#pragma unroll
            for (int j = 0; j < 4; j++) kv[j] = Ks[(tx * 4 + j) * APAD + d];
#pragma unroll
            for (int i = 0; i < 4; i++)
#pragma unroll
                for (int j = 0; j < 4; j++) s[i][j] += qv[i] * kv[j];
        }

        __syncthreads();          // all done reading Ks -> reuse as Ps
        float* Ps = Ks;
        const bool diag = (tk == tq);

        // Online softmax per owned row (16-lane row groups)
#pragma unroll
        for (int i = 0; i < 4; i++) {
            float sv[4];
#pragma unroll
            for (int j = 0; j < 4; j++) {
                float v = s[i][j] * 0.125f;   // 1/sqrt(64)
                if (diag && (tx * 4 + j) > (ty * 4 + i)) v = -1e30f;
                sv[j] = v;
            }
            float mloc = fmaxf(fmaxf(sv[0], sv[1]), fmaxf(sv[2], sv[3]));
#pragma unroll
            for (int off = 8; off > 0; off >>= 1)
                mloc = fmaxf(mloc, __shfl_xor_sync(0xffffffffu, mloc, off, 16));
            const float mnew = fmaxf(mrow[i], mloc);
            const float corr = __expf(mrow[i] - mnew);
            float psum = 0.f;
            float pv[4];
#pragma unroll
            for (int j = 0; j < 4; j++) {
                pv[j] = __expf(sv[j] - mnew);
                psum += pv[j];
            }
#pragma unroll
            for (int off = 8; off > 0; off >>= 1)
                psum += __shfl_xor_sync(0xffffffffu, psum, off, 16);
            lrow[i] = lrow[i] * corr + psum;
            mrow[i] = mnew;
#pragma unroll
            for (int j = 0; j < 4; j++) o[i][j] *= corr;
#pragma unroll
            for (int j = 0; j < 4; j++)
                Ps[(ty * 4 + i) * APAD + tx * 4 + j] = pv[j];
        }
        __syncthreads();

        // O += P V  (4x4 per thread; thread cols = head-dim tx*4..tx*4+3)
#pragma unroll 16
        for (int kk = 0; kk < 64; ++kk) {
            float p[4], v[4];
#pragma unroll
            for (int i = 0; i < 4; i++) p[i] = Ps[(ty * 4 + i) * APAD + kk];
#pragma unroll
            for (int j = 0; j < 4; j++) v[j] = Vs[kk * APAD + tx * 4 + j];
#pragma unroll
            for (int i = 0; i < 4; i++)
#pragma unroll
                for (int j = 0; j < 4; j++) o[i][j] += p[i] * v[j];
        }
        __syncthreads();   // before next tile overwrites Ks/Ps, Vs
    }

    // Normalize + write to g_att in [B,T,D]
    const int b = bh / NHEAD;
    const int h = bh % NHEAD;
#pragma unroll
    for (int i = 0; i < 4; i++) {
        const float inv = 1.f / lrow[i];
        const int t = q0 + ty * 4 + i;
#pragma unroll
        for (int j = 0; j < 4; j++) {
            g_att[((size_t)(b * SEQ + t)) * DMODEL + h * HDIM + tx * 4 + j] =
                o[i][j] * inv;
        }
    }
}

// ---------------------------------------------------------------------------
extern "C" void kernel_launch(void* const* d_in, const int* in_sizes, int n_in,
                              void* d_out, int out_size) {
    const float* x     = (const float*)d_in[0];
    const float* W_qkv = (const float*)d_in[1];
    const float* b_qkv = (const float*)d_in[2];
    const float* W_o   = (const float*)d_in[3];
    const float* b_o   = (const float*)d_in[4];
    float* out = (float*)d_out;

    // QKV projection: [8192,768] @ [768,2304]
    sgemm_qkv_kernel<<<dim3(2304 / 128, 8192 / 128), 256>>>(x, W_qkv, b_qkv);

    // Flash attention (causal), 49.9 KB dynamic smem
    const int smem = 3 * ASZ * (int)sizeof(float);
    cudaFuncSetAttribute(attn_kernel,
                         cudaFuncAttributeMaxDynamicSharedMemorySize, smem);
    attn_kernel<<<dim3(SEQ / 64, BATCH * NHEAD), 256, smem>>>();

    // Output projection: [8192,768] @ [768,768]
    sgemm_out_kernel<<<dim3(DMODEL / 128, 8192 / 128), 256>>>(W_o, b_o, out);
}

// round 13
// speedup vs baseline: 1.2915x; 1.2915x over previous
#include <cuda_runtime.h>
#include <cuda_fp16.h>
#include <cstdint>

#define BATCH 4
#define SEQ   2048
#define DMODEL 768
#define NHEAD 12
#define HDIM  64

// Scratch (device globals: allocation-free rule)
__device__ float g_q[BATCH * NHEAD * SEQ * HDIM];     // [B,H,T,hd]
__device__ float g_k[BATCH * NHEAD * SEQ * HDIM];
__device__ float g_v[BATCH * NHEAD * SEQ * HDIM];
__device__ float g_att[BATCH * SEQ * DMODEL];         // [B,T,D]

// ---------------------------------------------------------------------------
// mma.sync m16n8k16 fp16 -> f32 (legacy HMMA; baseline PTX, compute_103-safe)
// ---------------------------------------------------------------------------
#define MMA_F16(d, a, b) \
    asm volatile( \
        "mma.sync.aligned.m16n8k16.row.col.f32.f16.f16.f32 " \
        "{%0,%1,%2,%3}, {%4,%5,%6,%7}, {%8,%9}, {%0,%1,%2,%3};" \
        : "+f"((d)[0]), "+f"((d)[1]), "+f"((d)[2]), "+f"((d)[3]) \
        : "r"((a)[0]), "r"((a)[1]), "r"((a)[2]), "r"((a)[3]), \
          "r"((b)[0]), "r"((b)[1]))

__device__ __forceinline__ uint32_t pack_h2(float lo, float hi) {
    __half2 t = __floats2half2_rn(lo, hi);   // .x = lo (low 16 bits)
    return *reinterpret_cast<uint32_t*>(&t);
}

// ---------------------------------------------------------------------------
// fp16-split GEMM: C[8192, Ntot] = A[8192,768] @ W[768,Ntot] + bias
// CTA 128x128, BK=32, 256 thr = 8 warps (2M x 4N), warp tile 64x32.
// Split: C ~= Ah*Bh + Al*Bh + Ah*Bl  (rel err ~1e-5)
// mode 0: A = x (arg), scatter into g_q/g_k/g_v ([B,H,T,hd])
// mode 1: A = g_att (resolved IN DEVICE CODE - __device__ symbol must not be
//         evaluated host-side: host shadow is ATS-readable zeros on GB300),
//         write to out.
// ---------------------------------------------------------------------------
#define KP 34   // padded k-stride in fp16 elems (17 banks, odd -> low conflicts)

__global__ __launch_bounds__(256) void mma_gemm_kernel(
    const float* __restrict__ Ain, const float* __restrict__ W,
    const float* __restrict__ bias, float* __restrict__ out,
    int Ntot, int mode)
{
    __shared__ __align__(16) uint16_t Ah[128 * KP];
    __shared__ __align__(16) uint16_t Al[128 * KP];
    __shared__ __align__(16) uint16_t Bh[128 * KP];   // stored transposed: [n][k]
    __shared__ __align__(16) uint16_t Bl[128 * KP];

    // THE FIX: resolve g_att on the device side for mode 1.
    const float* A = (mode == 1) ? (const float*)g_att : Ain;

    const int tid = threadIdx.x;
    const int w   = tid >> 5;
    const int lid = tid & 31;
    const int wm  = w & 1;              // 0..1  (M groups of 64)
    const int wn  = w >> 1;             // 0..3  (N groups of 32)
    const int g   = lid >> 2;           // 0..7
    const int tg  = lid & 3;            // 0..3

    const int bm = blockIdx.y * 128;
    const int bn = blockIdx.x * 128;

    float acc[4][4][4];
#pragma unroll
    for (int mi = 0; mi < 4; mi++)
#pragma unroll
        for (int ni = 0; ni < 4; ni++)
#pragma unroll
            for (int c = 0; c < 4; c++) acc[mi][ni][c] = 0.f;

    const int nloc = tid & 127;         // B loader: n within tile
    const int kh   = tid >> 7;          // 0..1 -> k half (16 each)

    for (int it = 0; it < 24; ++it) {
        const int k0 = it * 32;

        // ---- A tile: 128x32 fp32 -> fp16 hi/lo, row-major [m][k] ----
#pragma unroll
        for (int r = 0; r < 4; r++) {
            const int f   = tid + 256 * r;
            const int row = f >> 3;            // 0..127
            const int c4  = (f & 7) * 4;       // 0..28
            float4 v = *(const float4*)&A[(size_t)(bm + row) * DMODEL + k0 + c4];
            __half h0 = __float2half_rn(v.x);
            __half h1 = __float2half_rn(v.y);
            __half h2 = __float2half_rn(v.z);
            __half h3 = __float2half_rn(v.w);
            const int base = row * KP + c4;
            __half2 p01 = __halves2half2(h0, h1);
            __half2 p23 = __halves2half2(h2, h3);
            *(uint32_t*)&Ah[base]     = *(uint32_t*)&p01;
            *(uint32_t*)&Ah[base + 2] = *(uint32_t*)&p23;
            *(uint32_t*)&Al[base]     = pack_h2(v.x - __half2float(h0),
                                                v.y - __half2float(h1));
            *(uint32_t*)&Al[base + 2] = pack_h2(v.z - __half2float(h2),
                                                v.w - __half2float(h3));
        }

        // ---- B tile: W[k][n] -> transposed smem [n][k], fp16 hi/lo ----
        {
            const float* wp = W + (size_t)(k0 + kh * 16) * Ntot + bn + nloc;
#pragma unroll
            for (int kk = 0; kk < 16; kk += 2) {
                float w0 = wp[(size_t)kk * Ntot];
                float w1 = wp[(size_t)(kk + 1) * Ntot];
                __half h0 = __float2half_rn(w0);
                __half h1 = __float2half_rn(w1);
                const int base = nloc * KP + kh * 16 + kk;
                __half2 ph = __halves2half2(h0, h1);
                *(uint32_t*)&Bh[base] = *(uint32_t*)&ph;
                *(uint32_t*)&Bl[base] = pack_h2(w0 - __half2float(h0),
                                                w1 - __half2float(h1));
            }
        }
        __syncthreads();

        // ---- 2 x k16 steps: load fragments, 48 MMAs each ----
#pragma unroll
        for (int s = 0; s < 2; ++s) {
            const int ks = s * 16;
            uint32_t ah[4][4], al[4][4], bhf[4][2], blf[4][2];
#pragma unroll
            for (int mi = 0; mi < 4; mi++) {
                const int r0 = (wm * 64 + mi * 16 + g) * KP + ks + tg * 2;
                const int r1 = r0 + 8 * KP;
                ah[mi][0] = *(const uint32_t*)&Ah[r0];
                ah[mi][1] = *(const uint32_t*)&Ah[r1];
                ah[mi][2] = *(const uint32_t*)&Ah[r0 + 8];
                ah[mi][3] = *(const uint32_t*)&Ah[r1 + 8];
                al[mi][0] = *(const uint32_t*)&Al[r0];
                al[mi][1] = *(const uint32_t*)&Al[r1];
                al[mi][2] = *(const uint32_t*)&Al[r0 + 8];
                al[mi][3] = *(const uint32_t*)&Al[r1 + 8];
            }
#pragma unroll
            for (int ni = 0; ni < 4; ni++) {
                const int b0 = (wn * 32 + ni * 8 + g) * KP + ks + tg * 2;
                bhf[ni][0] = *(const uint32_t*)&Bh[b0];
                bhf[ni][1] = *(const uint32_t*)&Bh[b0 + 8];
                blf[ni][0] = *(const uint32_t*)&Bl[b0];
                blf[ni][1] = *(const uint32_t*)&Bl[b0 + 8];
            }
#pragma unroll
            for (int mi = 0; mi < 4; mi++)
#pragma unroll
                for (int ni = 0; ni < 4; ni++) {
                    MMA_F16(acc[mi][ni], ah[mi], bhf[ni]);
                    MMA_F16(acc[mi][ni], al[mi], bhf[ni]);
                    MMA_F16(acc[mi][ni], ah[mi], blf[ni]);
                }
        }
        __syncthreads();
    }

    // ---- Epilogue: C fragment -> global (bias + optional q/k/v scatter) ----
    const int sel = bn / DMODEL;     // uniform per CTA (mode 0)
#pragma unroll
    for (int ni = 0; ni < 4; ni++) {
        const int n0 = bn + wn * 32 + ni * 8 + tg * 2;
        const float b0v = __ldg(&bias[n0]);
        const float b1v = __ldg(&bias[n0 + 1]);
#pragma unroll
        for (int mi = 0; mi < 4; mi++) {
            const int m0 = bm + wm * 64 + mi * 16 + g;
#pragma unroll
            for (int hrow = 0; hrow < 2; hrow++) {
                const int m = m0 + hrow * 8;
                const float v0 = acc[mi][ni][hrow * 2 + 0] + b0v;
                const float v1 = acc[mi][ni][hrow * 2 + 1] + b1v;
                if (mode == 0) {
                    const int bb = m >> 11;
                    const int tt = m & 2047;
                    const int nn = n0 - sel * DMODEL;
                    const int hh = nn >> 6;
                    const int dd = nn & 63;
                    float* dst = (sel == 0) ? g_q : (sel == 1) ? g_k : g_v;
                    float2* p = (float2*)&dst[(((size_t)(bb * NHEAD + hh)) * SEQ + tt) * HDIM + dd];
                    *p = make_float2(v0, v1);
                } else {
                    float2* p = (float2*)&out[(size_t)m * DMODEL + n0];
                    *p = make_float2(v0, v1);
                }
            }
        }
    }
}

// ---------------------------------------------------------------------------
// Kernel 2: flash attention, fp32, causal (proven round-1 version, unchanged).
// ---------------------------------------------------------------------------
#define APAD 65
#define ASZ (64 * APAD)

__global__ __launch_bounds__(256) void attn_kernel() {
    extern __shared__ float sm[];
    float* Qs = sm;
    float* Ks = sm + ASZ;
    float* Vs = sm + 2 * ASZ;

    const int tq = blockIdx.x;
    const int bh = blockIdx.y;
    const int q0 = tq * 64;
    const float* Qg = g_q + (size_t)bh * SEQ * HDIM;
    const float* Kg = g_k + (size_t)bh * SEQ * HDIM;
    const float* Vg = g_v + (size_t)bh * SEQ * HDIM;

    const int tid = threadIdx.x;
    const int ty = tid >> 4;
    const int tx = tid & 15;

#pragma unroll
    for (int r = 0; r < 4; r++) {
        const int f = tid + 256 * r;
        const int row = f >> 4;
        const int d0 = (f & 15) * 4;
        float4 q = *(const float4*)&Qg[(size_t)(q0 + row) * HDIM + d0];
        float* p = &Qs[row * APAD + d0];
        p[0] = q.x; p[1] = q.y; p[2] = q.z; p[3] = q.w;
    }

    float o[4][4];
    float mrow[4], lrow[4];
#pragma unroll
    for (int i = 0; i < 4; i++) {
        mrow[i] = -1e30f;
        lrow[i] = 0.f;
#pragma unroll
        for (int j = 0; j < 4; j++) o[i][j] = 0.f;
    }
    __syncthreads();

    for (int tk = 0; tk <= tq; ++tk) {
        const int k0 = tk * 64;
#pragma unroll
        for (int r = 0; r < 4; r++) {
            const int f = tid + 256 * r;
            const int row = f >> 4;
            const int d0 = (f & 15) * 4;
            float4 kv = *(const float4*)&Kg[(size_t)(k0 + row) * HDIM + d0];
            float4 vv = *(const float4*)&Vg[(size_t)(k0 + row) * HDIM + d0];
            float* pk = &Ks[row * APAD + d0];
            pk[0] = kv.x; pk[1] = kv.y; pk[2] = kv.z; pk[3] = kv.w;
            float* pv = &Vs[row * APAD + d0];
            pv[0] = vv.x; pv[1] = vv.y; pv[2] = vv.z; pv[3] = vv.w;
        }
        __syncthreads();

        float s[4][4];
#pragma unroll
        for (int i = 0; i < 4; i++)
#pragma unroll
            for (int j = 0; j < 4; j++) s[i][j] = 0.f;

#pragma unroll 16
        for (int d = 0; d < HDIM; ++d) {
            float qv[4], kv[4];
#pragma unroll
            for (int i = 0; i < 4; i++) qv[i] = Qs[(ty * 4 + i) * APAD + d];
#pragma unroll
            for (int j = 0; j < 4; j++) kv[j] = Ks[(tx * 4 + j) * APAD + d];
#pragma unroll
            for (int i = 0; i < 4; i++)
#pragma unroll
                for (int j = 0; j < 4; j++) s[i][j] += qv[i] * kv[j];
        }

        __syncthreads();
        float* Ps = Ks;
        const bool diag = (tk == tq);

#pragma unroll
        for (int i = 0; i < 4; i++) {
            float sv[4];
#pragma unroll
            for (int j = 0; j < 4; j++) {
                float v = s[i][j] * 0.125f;
                if (diag && (tx * 4 + j) > (ty * 4 + i)) v = -1e30f;
                sv[j] = v;
            }
            float mloc = fmaxf(fmaxf(sv[0], sv[1]), fmaxf(sv[2], sv[3]));
#pragma unroll
            for (int off = 8; off > 0; off >>= 1)
                mloc = fmaxf(mloc, __shfl_xor_sync(0xffffffffu, mloc, off, 16));
            const float mnew = fmaxf(mrow[i], mloc);
            const float corr = __expf(mrow[i] - mnew);
            float psum = 0.f;
            float pv[4];
#pragma unroll
            for (int j = 0; j < 4; j++) {
                pv[j] = __expf(sv[j] - mnew);
                psum += pv[j];
            }
#pragma unroll
            for (int off = 8; off > 0; off >>= 1)
                psum += __shfl_xor_sync(0xffffffffu, psum, off, 16);
            lrow[i] = lrow[i] * corr + psum;
            mrow[i] = mnew;
#pragma unroll
            for (int j = 0; j < 4; j++) o[i][j] *= corr;
#pragma unroll
            for (int j = 0; j < 4; j++)
                Ps[(ty * 4 + i) * APAD + tx * 4 + j] = pv[j];
        }
        __syncthreads();

#pragma unroll 16
        for (int kk = 0; kk < 64; ++kk) {
            float p[4], v[4];
#pragma unroll
            for (int i = 0; i < 4; i++) p[i] = Ps[(ty * 4 + i) * APAD + kk];
#pragma unroll
            for (int j = 0; j < 4; j++) v[j] = Vs[kk * APAD + tx * 4 + j];
#pragma unroll
            for (int i = 0; i < 4; i++)
#pragma unroll
                for (int j = 0; j < 4; j++) o[i][j] += p[i] * v[j];
        }
        __syncthreads();
    }

    const int b = bh / NHEAD;
    const int h = bh % NHEAD;
#pragma unroll
    for (int i = 0; i < 4; i++) {
        const float inv = 1.f / lrow[i];
        const int t = q0 + ty * 4 + i;
#pragma unroll
        for (int j = 0; j < 4; j++) {
            g_att[((size_t)(b * SEQ + t)) * DMODEL + h * HDIM + tx * 4 + j] =
                o[i][j] * inv;
        }
    }
}

// ---------------------------------------------------------------------------
extern "C" void kernel_launch(void* const* d_in, const int* in_sizes, int n_in,
                              void* d_out, int out_size) {
    const float* x     = (const float*)d_in[0];
    const float* W_qkv = (const float*)d_in[1];
    const float* b_qkv = (const float*)d_in[2];
    const float* W_o   = (const float*)d_in[3];
    const float* b_o   = (const float*)d_in[4];
    float* out = (float*)d_out;

    // QKV projection: [8192,768] @ [768,2304] -> scatter q/k/v
    mma_gemm_kernel<<<dim3(2304 / 128, 8192 / 128), 256>>>(
        x, W_qkv, b_qkv, nullptr, 2304, 0);

    // Flash attention (causal), 49.9 KB dynamic smem
    const int smem = 3 * ASZ * (int)sizeof(float);
    cudaFuncSetAttribute(attn_kernel,
                         cudaFuncAttributeMaxDynamicSharedMemorySize, smem);
    attn_kernel<<<dim3(SEQ / 64, BATCH * NHEAD), 256, smem>>>();

    // Output projection: [8192,768] @ [768,768]  (A resolved in-kernel)
    mma_gemm_kernel<<<dim3(DMODEL / 128, 8192 / 128), 256>>>(
        nullptr, W_o, b_o, out, DMODEL, 1);
}